// round 1
// baseline (speedup 1.0000x reference)
#include <cuda_runtime.h>
#include <math.h>

// Problem constants
#define BB 4
#define SS 4096
#define DD 512
#define M_TOTAL (BB * SS)   // 16384

// Scratch (allocation-free rule: __device__ globals)
__device__ float g_Q[(size_t)M_TOTAL * DD];          // 33.5 MB
__device__ float g_K[(size_t)M_TOTAL * DD];          // 33.5 MB
__device__ float g_V[(size_t)M_TOTAL * DD];          // 33.5 MB
__device__ float g_P[(size_t)BB * SS * SS];          // 268 MB (sigmoid weights)

// Tile config (shared by all three GEMMs)
#define BM 128
#define BN 128
#define BK 8
#define TM 8
#define TN 8
#define NTHREADS 256

#define INV_SQRT_D 0.04419417382415922f   // 1/sqrt(512)

// ---------------------------------------------------------------------------
// Kernel 1: fused QKV projection.  C[m,n] = sum_k x[m,k] * W[n,k] + b[n]
// NT GEMM: M=16384, N=512, K=512. grid.z in {0,1,2} selects (Wq,Wk,Wv).
// ---------------------------------------------------------------------------
__global__ void __launch_bounds__(NTHREADS)
qkv_kernel(const float* __restrict__ x,
           const float* __restrict__ Wq, const float* __restrict__ bq,
           const float* __restrict__ Wk, const float* __restrict__ bk,
           const float* __restrict__ Wv, const float* __restrict__ bv)
{
    const float* W;
    const float* bvec;
    float* C;
    if (blockIdx.z == 0)      { W = Wq; bvec = bq; C = g_Q; }
    else if (blockIdx.z == 1) { W = Wk; bvec = bk; C = g_K; }
    else                      { W = Wv; bvec = bv; C = g_V; }

    __shared__ float As[BK][BM];
    __shared__ float Bs[BK][BN];

    const int tid = threadIdx.x;
    const int rowBase = blockIdx.y * BM;
    const int colBase = blockIdx.x * BN;

    const int ldRow = tid >> 1;           // 0..127
    const int ldCol = (tid & 1) * 4;      // 0 or 4

    const int ty = tid >> 4;              // 0..15
    const int tx = tid & 15;              // 0..15

    float acc[TM][TN];
#pragma unroll
    for (int i = 0; i < TM; i++)
#pragma unroll
        for (int j = 0; j < TN; j++) acc[i][j] = 0.0f;

    for (int k0 = 0; k0 < DD; k0 += BK) {
        float4 av = *(const float4*)(x + (size_t)(rowBase + ldRow) * DD + k0 + ldCol);
        float4 bv4 = *(const float4*)(W + (size_t)(colBase + ldRow) * DD + k0 + ldCol);
        __syncthreads();
        As[ldCol + 0][ldRow] = av.x;  As[ldCol + 1][ldRow] = av.y;
        As[ldCol + 2][ldRow] = av.z;  As[ldCol + 3][ldRow] = av.w;
        Bs[ldCol + 0][ldRow] = bv4.x; Bs[ldCol + 1][ldRow] = bv4.y;
        Bs[ldCol + 2][ldRow] = bv4.z; Bs[ldCol + 3][ldRow] = bv4.w;
        __syncthreads();
#pragma unroll
        for (int k = 0; k < BK; k++) {
            float a[TM], b[TN];
            *(float4*)(a)     = *(const float4*)&As[k][ty * TM];
            *(float4*)(a + 4) = *(const float4*)&As[k][ty * TM + 4];
            *(float4*)(b)     = *(const float4*)&Bs[k][tx * TN];
            *(float4*)(b + 4) = *(const float4*)&Bs[k][tx * TN + 4];
#pragma unroll
            for (int i = 0; i < TM; i++)
#pragma unroll
                for (int j = 0; j < TN; j++) acc[i][j] += a[i] * b[j];
        }
    }

    // epilogue: + bias, store
#pragma unroll
    for (int i = 0; i < TM; i++) {
        int r = rowBase + ty * TM + i;
        int c0 = colBase + tx * TN;
        float4 o0, o1;
        o0.x = acc[i][0] + bvec[c0 + 0]; o0.y = acc[i][1] + bvec[c0 + 1];
        o0.z = acc[i][2] + bvec[c0 + 2]; o0.w = acc[i][3] + bvec[c0 + 3];
        o1.x = acc[i][4] + bvec[c0 + 4]; o1.y = acc[i][5] + bvec[c0 + 5];
        o1.z = acc[i][6] + bvec[c0 + 6]; o1.w = acc[i][7] + bvec[c0 + 7];
        *(float4*)(C + (size_t)r * DD + c0)     = o0;
        *(float4*)(C + (size_t)r * DD + c0 + 4) = o1;
    }
}

// ---------------------------------------------------------------------------
// Kernel 2: P[b,q,k] = sigmoid( (Q_b · K_b^T)[q,k] * inv_sqrt_d + bias[q,k] )
// NT GEMM: M=N=4096, K=512, batched over grid.z = b.
// ---------------------------------------------------------------------------
__global__ void __launch_bounds__(NTHREADS)
scores_kernel(const float* __restrict__ bias)
{
    const int b = blockIdx.z;
    const float* A = g_Q + (size_t)b * SS * DD;
    const float* Bm = g_K + (size_t)b * SS * DD;
    float* P = g_P + (size_t)b * SS * SS;

    __shared__ float As[BK][BM];
    __shared__ float Bs[BK][BN];

    const int tid = threadIdx.x;
    const int rowBase = blockIdx.y * BM;
    const int colBase = blockIdx.x * BN;

    const int ldRow = tid >> 1;
    const int ldCol = (tid & 1) * 4;
    const int ty = tid >> 4;
    const int tx = tid & 15;

    float acc[TM][TN];
#pragma unroll
    for (int i = 0; i < TM; i++)
#pragma unroll
        for (int j = 0; j < TN; j++) acc[i][j] = 0.0f;

    for (int k0 = 0; k0 < DD; k0 += BK) {
        float4 av = *(const float4*)(A + (size_t)(rowBase + ldRow) * DD + k0 + ldCol);
        float4 bv4 = *(const float4*)(Bm + (size_t)(colBase + ldRow) * DD + k0 + ldCol);
        __syncthreads();
        As[ldCol + 0][ldRow] = av.x;  As[ldCol + 1][ldRow] = av.y;
        As[ldCol + 2][ldRow] = av.z;  As[ldCol + 3][ldRow] = av.w;
        Bs[ldCol + 0][ldRow] = bv4.x; Bs[ldCol + 1][ldRow] = bv4.y;
        Bs[ldCol + 2][ldRow] = bv4.z; Bs[ldCol + 3][ldRow] = bv4.w;
        __syncthreads();
#pragma unroll
        for (int k = 0; k < BK; k++) {
            float a[TM], bb[TN];
            *(float4*)(a)      = *(const float4*)&As[k][ty * TM];
            *(float4*)(a + 4)  = *(const float4*)&As[k][ty * TM + 4];
            *(float4*)(bb)     = *(const float4*)&Bs[k][tx * TN];
            *(float4*)(bb + 4) = *(const float4*)&Bs[k][tx * TN + 4];
#pragma unroll
            for (int i = 0; i < TM; i++)
#pragma unroll
                for (int j = 0; j < TN; j++) acc[i][j] += a[i] * bb[j];
        }
    }

    // epilogue: scale + bias + sigmoid, store P
#pragma unroll
    for (int i = 0; i < TM; i++) {
        int r = rowBase + ty * TM + i;
        int c0 = colBase + tx * TN;
        const float* brow = bias + (size_t)r * SS + c0;
        float o[TN];
#pragma unroll
        for (int j = 0; j < TN; j++) {
            float v = acc[i][j] * INV_SQRT_D + brow[j];
            o[j] = 1.0f / (1.0f + __expf(-v));
        }
        *(float4*)(P + (size_t)r * SS + c0)     = *(float4*)(o);
        *(float4*)(P + (size_t)r * SS + c0 + 4) = *(float4*)(o + 4);
    }
}

// ---------------------------------------------------------------------------
// Kernel 3: out[b,q,d] = sum_k P[b,q,k] * V[b,k,d]
// NN GEMM: M=4096, N=512, K=4096, batched over grid.z = b.
// ---------------------------------------------------------------------------
__global__ void __launch_bounds__(NTHREADS)
out_kernel(float* __restrict__ out)
{
    const int b = blockIdx.z;
    const float* A = g_P + (size_t)b * SS * SS;    // lda = 4096
    const float* Bm = g_V + (size_t)b * SS * DD;   // ldb = 512

    __shared__ float As[BK][BM];
    __shared__ float Bs[BK][BN];

    const int tid = threadIdx.x;
    const int rowBase = blockIdx.y * BM;
    const int colBase = blockIdx.x * BN;

    const int ldRow = tid >> 1;          // A loader: 0..127
    const int ldCol = (tid & 1) * 4;
    const int bRow = tid >> 5;           // B loader: 0..7
    const int bCol = (tid & 31) * 4;     // 0..124

    const int ty = tid >> 4;
    const int tx = tid & 15;

    float acc[TM][TN];
#pragma unroll
    for (int i = 0; i < TM; i++)
#pragma unroll
        for (int j = 0; j < TN; j++) acc[i][j] = 0.0f;

    for (int k0 = 0; k0 < SS; k0 += BK) {
        float4 av = *(const float4*)(A + (size_t)(rowBase + ldRow) * SS + k0 + ldCol);
        float4 bv4 = *(const float4*)(Bm + (size_t)(k0 + bRow) * DD + colBase + bCol);
        __syncthreads();
        As[ldCol + 0][ldRow] = av.x;  As[ldCol + 1][ldRow] = av.y;
        As[ldCol + 2][ldRow] = av.z;  As[ldCol + 3][ldRow] = av.w;
        *(float4*)&Bs[bRow][bCol] = bv4;   // V already k-major rows
        __syncthreads();
#pragma unroll
        for (int k = 0; k < BK; k++) {
            float a[TM], bb[TN];
            *(float4*)(a)      = *(const float4*)&As[k][ty * TM];
            *(float4*)(a + 4)  = *(const float4*)&As[k][ty * TM + 4];
            *(float4*)(bb)     = *(const float4*)&Bs[k][tx * TN];
            *(float4*)(bb + 4) = *(const float4*)&Bs[k][tx * TN + 4];
#pragma unroll
            for (int i = 0; i < TM; i++)
#pragma unroll
                for (int j = 0; j < TN; j++) acc[i][j] += a[i] * bb[j];
        }
    }

#pragma unroll
    for (int i = 0; i < TM; i++) {
        int r = rowBase + ty * TM + i;
        int c0 = colBase + tx * TN;
        *(float4*)(out + ((size_t)b * SS + r) * DD + c0)     = *(float4*)(&acc[i][0]);
        *(float4*)(out + ((size_t)b * SS + r) * DD + c0 + 4) = *(float4*)(&acc[i][4]);
    }
}

// ---------------------------------------------------------------------------
extern "C" void kernel_launch(void* const* d_in, const int* in_sizes, int n_in,
                              void* d_out, int out_size)
{
    const float* x    = (const float*)d_in[0];
    const float* bias = (const float*)d_in[1];
    const float* Wq   = (const float*)d_in[2];
    const float* bq   = (const float*)d_in[3];
    const float* Wk   = (const float*)d_in[4];
    const float* bk   = (const float*)d_in[5];
    const float* Wv   = (const float*)d_in[6];
    const float* bv   = (const float*)d_in[7];
    float* out = (float*)d_out;

    // 1) QKV projections: M=16384, N=512 -> grid (4, 128, 3)
    qkv_kernel<<<dim3(DD / BN, M_TOTAL / BM, 3), NTHREADS>>>(x, Wq, bq, Wk, bk, Wv, bv);

    // 2) sigmoid scores: M=N=4096 per batch -> grid (32, 32, 4)
    scores_kernel<<<dim3(SS / BN, SS / BM, BB), NTHREADS>>>(bias);

    // 3) out = P @ V: M=4096, N=512 per batch -> grid (4, 32, 4)
    out_kernel<<<dim3(DD / BN, SS / BM, BB), NTHREADS>>>(out);
}

// round 3
// speedup vs baseline: 2.7414x; 2.7414x over previous
#include <cuda_runtime.h>
#include <cuda_bf16.h>
#include <stdint.h>
#include <math.h>

// ---------------------------------------------------------------------------
// Problem constants
// ---------------------------------------------------------------------------
#define BB 4
#define SS 4096
#define DD 512
#define M_TOTAL (BB * SS)   // 16384
#define INV_SQRT_D 0.04419417382415922f

// ---------------------------------------------------------------------------
// Scratch (__device__ globals; allocation-free rule). 16B-aligned for cp.async.
// ---------------------------------------------------------------------------
__device__ __align__(256) __nv_bfloat16 g_xhi[(size_t)M_TOTAL * DD];
__device__ __align__(256) __nv_bfloat16 g_xlo[(size_t)M_TOTAL * DD];
__device__ __align__(256) __nv_bfloat16 g_Whi[(size_t)3 * DD * DD];
__device__ __align__(256) __nv_bfloat16 g_Wlo[(size_t)3 * DD * DD];
__device__ __align__(256) __nv_bfloat16 g_Qhi[(size_t)M_TOTAL * DD];
__device__ __align__(256) __nv_bfloat16 g_Qlo[(size_t)M_TOTAL * DD];
__device__ __align__(256) __nv_bfloat16 g_Khi[(size_t)M_TOTAL * DD];
__device__ __align__(256) __nv_bfloat16 g_Klo[(size_t)M_TOTAL * DD];
__device__ __align__(256) float         g_Vf [(size_t)M_TOTAL * DD];
__device__ __align__(256) __nv_bfloat16 g_Vthi[(size_t)BB * DD * SS];  // V^T [b][d][s]
__device__ __align__(256) __nv_bfloat16 g_Vtlo[(size_t)BB * DD * SS];
__device__ __align__(256) __nv_bfloat16 g_Phi[(size_t)BB * SS * SS];
__device__ __align__(256) __nv_bfloat16 g_Plo[(size_t)BB * SS * SS];

// ---------------------------------------------------------------------------
// Helpers
// ---------------------------------------------------------------------------
__device__ __forceinline__ uint32_t smem_u32(const void* p) {
    uint32_t a;
    asm("{ .reg .u64 t; cvta.to.shared.u64 t, %1; cvt.u32.u64 %0, t; }" : "=r"(a) : "l"(p));
    return a;
}

#define CP_ASYNC16(dst, src) \
    asm volatile("cp.async.cg.shared.global [%0], [%1], 16;" :: "r"(dst), "l"(src))
#define CP_COMMIT() asm volatile("cp.async.commit_group;")
#define CP_WAIT1()  asm volatile("cp.async.wait_group 1;" ::: "memory")
#define CP_WAIT0()  asm volatile("cp.async.wait_group 0;" ::: "memory")

__device__ __forceinline__ void ldsm4(uint32_t (&r)[4], uint32_t addr) {
    asm volatile("ldmatrix.sync.aligned.m8n8.x4.shared.b16 {%0,%1,%2,%3}, [%4];"
                 : "=r"(r[0]), "=r"(r[1]), "=r"(r[2]), "=r"(r[3]) : "r"(addr));
}

__device__ __forceinline__ void mma16816(float (&d)[4], const uint32_t (&a)[4],
                                         uint32_t b0, uint32_t b1) {
    asm volatile(
        "mma.sync.aligned.m16n8k16.row.col.f32.bf16.bf16.f32 "
        "{%0,%1,%2,%3}, {%4,%5,%6,%7}, {%8,%9}, {%0,%1,%2,%3};"
        : "+f"(d[0]), "+f"(d[1]), "+f"(d[2]), "+f"(d[3])
        : "r"(a[0]), "r"(a[1]), "r"(a[2]), "r"(a[3]), "r"(b0), "r"(b1));
}

__device__ __forceinline__ void split_bf16(float v, __nv_bfloat16& h, __nv_bfloat16& l) {
    h = __float2bfloat16(v);
    l = __float2bfloat16(v - __bfloat162float(h));
}
__device__ __forceinline__ uint32_t pack2(__nv_bfloat16 a, __nv_bfloat16 b) {
    return ((uint32_t)__bfloat16_as_ushort(b) << 16) | (uint32_t)__bfloat16_as_ushort(a);
}

// ---------------------------------------------------------------------------
// Shared mma.sync GEMM core.
// NT GEMM: A[M,K] row-major (hi/lo), B[N,K] row-major (hi/lo), bf16.
// CTA tile 128x128, BK=32, 256 threads (8 warps as 4x2 of 32x64 warp tiles).
// SMEM per stage 32KB: Ahi | Alo | Bhi | Blo (8KB each), 2 stages.
// 64B rows (32 bf16), XOR swizzle chunk ^= (row>>1)&3 for conflict-free ldmatrix.
// ---------------------------------------------------------------------------
#define STAGE_BYTES 32768
#define SMEM_GEMM (2 * STAGE_BYTES)

__device__ __forceinline__ void load_stage(
    uint32_t sb, const __nv_bfloat16* Ah, const __nv_bfloat16* Al, int lda,
    const __nv_bfloat16* Bh, const __nv_bfloat16* Bl, int ldb, int k0, int tid)
{
#pragma unroll
    for (int it = 0; it < 2; ++it) {
        int u = it * 256 + tid;            // 0..511
        int row = u >> 2;                  // 0..127
        int ch = u & 3;                    // 16B chunk in 64B row
        uint32_t soff = (uint32_t)row * 64 + ((uint32_t)(ch ^ ((row >> 1) & 3)) << 4);
        const char* ga  = (const char*)(Ah + (size_t)row * lda + k0) + ch * 16;
        const char* gal = (const char*)(Al + (size_t)row * lda + k0) + ch * 16;
        const char* gb  = (const char*)(Bh + (size_t)row * ldb + k0) + ch * 16;
        const char* gbl = (const char*)(Bl + (size_t)row * ldb + k0) + ch * 16;
        CP_ASYNC16(sb +         soff, ga);
        CP_ASYNC16(sb +  8192 + soff, gal);
        CP_ASYNC16(sb + 16384 + soff, gb);
        CP_ASYNC16(sb + 24576 + soff, gbl);
    }
}

template<int KTILES>
__device__ __forceinline__ void gemm_core(
    const __nv_bfloat16* __restrict__ Ah, const __nv_bfloat16* __restrict__ Al, int lda,
    const __nv_bfloat16* __restrict__ Bh, const __nv_bfloat16* __restrict__ Bl, int ldb,
    uint32_t sbase, float (&acc)[16][4])
{
    const int tid  = threadIdx.x;
    const int lane = tid & 31;
    const int wid  = tid >> 5;
    const int warpM = wid >> 1;   // 0..3
    const int warpN = wid & 1;    // 0..1

#pragma unroll
    for (int i = 0; i < 16; ++i)
#pragma unroll
        for (int j = 0; j < 4; ++j) acc[i][j] = 0.0f;

    load_stage(sbase, Ah, Al, lda, Bh, Bl, ldb, 0, tid);
    CP_COMMIT();

    const int arow = warpM * 32 + (lane & 15);
    const uint32_t a_sw = (uint32_t)((arow >> 1) & 3);
    const int ach = lane >> 4;                       // 0/1: k half
    const int brow = warpN * 64 + ((lane >> 4) << 3) + (lane & 7);
    const uint32_t b_sw = (uint32_t)((brow >> 1) & 3);
    const int bch = (lane >> 3) & 1;

#pragma unroll 1
    for (int kt = 0; kt < KTILES; ++kt) {
        if (kt > 0) __syncthreads();   // stage buffer reuse barrier
        if (kt + 1 < KTILES) {
            load_stage(sbase + ((kt + 1) & 1) * STAGE_BYTES,
                       Ah, Al, lda, Bh, Bl, ldb, (kt + 1) * 32, tid);
            CP_COMMIT();
            CP_WAIT1();
        } else {
            CP_WAIT0();
        }
        __syncthreads();

        uint32_t sb = sbase + (uint32_t)(kt & 1) * STAGE_BYTES;
#pragma unroll
        for (int ks = 0; ks < 2; ++ks) {
            uint32_t ah[2][4], al[2][4], bh[4][4], bl[4][4];
#pragma unroll
            for (int mt = 0; mt < 2; ++mt) {
                uint32_t addr = sb + (uint32_t)(arow + mt * 16) * 64 +
                                (((uint32_t)(ks * 2 + ach)) ^ a_sw) * 16;
                ldsm4(ah[mt], addr);
                ldsm4(al[mt], addr + 8192);
            }
#pragma unroll
            for (int nb = 0; nb < 4; ++nb) {
                uint32_t addr = sb + 16384 + (uint32_t)(brow + nb * 16) * 64 +
                                (((uint32_t)(ks * 2 + bch)) ^ b_sw) * 16;
                ldsm4(bh[nb], addr);
                ldsm4(bl[nb], addr + 8192);
            }
#pragma unroll
            for (int mt = 0; mt < 2; ++mt)
#pragma unroll
                for (int nt = 0; nt < 8; ++nt) {
                    uint32_t h0 = bh[nt >> 1][(nt & 1) * 2];
                    uint32_t h1 = bh[nt >> 1][(nt & 1) * 2 + 1];
                    uint32_t l0 = bl[nt >> 1][(nt & 1) * 2];
                    uint32_t l1 = bl[nt >> 1][(nt & 1) * 2 + 1];
                    mma16816(acc[mt * 8 + nt], ah[mt], h0, h1);   // hi*hi
                    mma16816(acc[mt * 8 + nt], ah[mt], l0, l1);   // hi*lo
                    mma16816(acc[mt * 8 + nt], al[mt], h0, h1);   // lo*hi
                }
        }
    }
}

// ---------------------------------------------------------------------------
// Split kernel: fp32 -> bf16 hi/lo (elementwise, 4 per thread)
// ---------------------------------------------------------------------------
__global__ void __launch_bounds__(256)
split_kernel(const float* __restrict__ src, __nv_bfloat16* __restrict__ hi,
             __nv_bfloat16* __restrict__ lo, int n4)
{
    int i = blockIdx.x * 256 + threadIdx.x;
    if (i >= n4) return;
    float4 v = *(const float4*)(src + (size_t)i * 4);
    __nv_bfloat16 h0, l0, h1, l1, h2, l2, h3, l3;
    split_bf16(v.x, h0, l0); split_bf16(v.y, h1, l1);
    split_bf16(v.z, h2, l2); split_bf16(v.w, h3, l3);
    *(uint2*)(hi + (size_t)i * 4) = make_uint2(pack2(h0, h1), pack2(h2, h3));
    *(uint2*)(lo + (size_t)i * 4) = make_uint2(pack2(l0, l1), pack2(l2, l3));
}

// ---------------------------------------------------------------------------
// QKV projection: C = x @ W^T + b, grid.z selects (Q,K,V).
// Q scaled by 1/sqrt(D) then split; K split; V stored fp32 for transpose.
// ---------------------------------------------------------------------------
__global__ void __launch_bounds__(256, 1)
qkv_mma(const float* __restrict__ bq, const float* __restrict__ bk,
        const float* __restrict__ bv)
{
    extern __shared__ char smem[];
    uint32_t sbase = smem_u32(smem);
    const int z = blockIdx.z;
    const int mrow = blockIdx.y * 128;
    const int ncol = blockIdx.x * 128;

    const __nv_bfloat16* Ah = g_xhi + (size_t)mrow * DD;
    const __nv_bfloat16* Al = g_xlo + (size_t)mrow * DD;
    const __nv_bfloat16* Bh = g_Whi + (size_t)z * DD * DD + (size_t)ncol * DD;
    const __nv_bfloat16* Bl = g_Wlo + (size_t)z * DD * DD + (size_t)ncol * DD;

    float acc[16][4];
    gemm_core<DD / 32>(Ah, Al, DD, Bh, Bl, DD, sbase, acc);

    const float* bvec = (z == 0) ? bq : ((z == 1) ? bk : bv);
    const int lane = threadIdx.x & 31, wid = threadIdx.x >> 5;
    const int warpM = wid >> 1, warpN = wid & 1;

#pragma unroll
    for (int mt = 0; mt < 2; ++mt)
#pragma unroll
        for (int nt = 0; nt < 8; ++nt)
#pragma unroll
            for (int h = 0; h < 2; ++h) {
                int r = mrow + warpM * 32 + mt * 16 + (lane >> 2) + h * 8;
                int c = ncol + warpN * 64 + nt * 8 + (lane & 3) * 2;
                float v0 = acc[mt * 8 + nt][h * 2 + 0] + bvec[c];
                float v1 = acc[mt * 8 + nt][h * 2 + 1] + bvec[c + 1];
                size_t o = (size_t)r * DD + c;
                if (z == 2) {
                    *(float2*)(g_Vf + o) = make_float2(v0, v1);
                } else {
                    if (z == 0) { v0 *= INV_SQRT_D; v1 *= INV_SQRT_D; }
                    __nv_bfloat16 h0, l0, h1, l1;
                    split_bf16(v0, h0, l0);
                    split_bf16(v1, h1, l1);
                    __nv_bfloat16* hip = (z == 0) ? g_Qhi : g_Khi;
                    __nv_bfloat16* lop = (z == 0) ? g_Qlo : g_Klo;
                    *(uint32_t*)(hip + o) = pack2(h0, h1);
                    *(uint32_t*)(lop + o) = pack2(l0, l1);
                }
            }
}

// ---------------------------------------------------------------------------
// V transpose + split -> Vt[b][d][s] bf16 hi/lo
// ---------------------------------------------------------------------------
__global__ void __launch_bounds__(256)
vt_kernel()
{
    __shared__ float t[32][33];
    const int bxd = blockIdx.x;
    const int bys = blockIdx.y;
    const int bz  = blockIdx.z;
    const int tx = threadIdx.x & 31;
    const int ty = threadIdx.x >> 5;

    const float* src = g_Vf + (size_t)bz * SS * DD;
#pragma unroll
    for (int i = 0; i < 4; i++) {
        int s = bys * 32 + ty + i * 8;
        t[ty + i * 8][tx] = src[(size_t)s * DD + bxd * 32 + tx];
    }
    __syncthreads();
#pragma unroll
    for (int i = 0; i < 4; i++) {
        int d = bxd * 32 + ty + i * 8;
        float v = t[tx][ty + i * 8];
        __nv_bfloat16 h, l;
        split_bf16(v, h, l);
        size_t o = ((size_t)bz * DD + d) * SS + bys * 32 + tx;
        g_Vthi[o] = h;
        g_Vtlo[o] = l;
    }
}

// ---------------------------------------------------------------------------
// Scores: P = sigmoid(Q K^T + bias)  (Q already scaled), split -> Phi/Plo
// ---------------------------------------------------------------------------
__global__ void __launch_bounds__(256, 1)
scores_mma(const float* __restrict__ bias)
{
    extern __shared__ char smem[];
    uint32_t sbase = smem_u32(smem);
    const int bz = blockIdx.z;
    const int mrow = blockIdx.y * 128;
    const int ncol = blockIdx.x * 128;

    const __nv_bfloat16* Ah = g_Qhi + ((size_t)bz * SS + mrow) * DD;
    const __nv_bfloat16* Al = g_Qlo + ((size_t)bz * SS + mrow) * DD;
    const __nv_bfloat16* Bh = g_Khi + ((size_t)bz * SS + ncol) * DD;
    const __nv_bfloat16* Bl = g_Klo + ((size_t)bz * SS + ncol) * DD;

    float acc[16][4];
    gemm_core<DD / 32>(Ah, Al, DD, Bh, Bl, DD, sbase, acc);

    const int lane = threadIdx.x & 31, wid = threadIdx.x >> 5;
    const int warpM = wid >> 1, warpN = wid & 1;

#pragma unroll
    for (int mt = 0; mt < 2; ++mt)
#pragma unroll
        for (int nt = 0; nt < 8; ++nt)
#pragma unroll
            for (int h = 0; h < 2; ++h) {
                int r = mrow + warpM * 32 + mt * 16 + (lane >> 2) + h * 8;
                int c = ncol + warpN * 64 + nt * 8 + (lane & 3) * 2;
                float2 bb = *(const float2*)(bias + (size_t)r * SS + c);
                float v0 = acc[mt * 8 + nt][h * 2 + 0] + bb.x;
                float v1 = acc[mt * 8 + nt][h * 2 + 1] + bb.y;
                float s0 = __fdividef(1.0f, 1.0f + __expf(-v0));
                float s1 = __fdividef(1.0f, 1.0f + __expf(-v1));
                __nv_bfloat16 h0, l0, h1, l1;
                split_bf16(s0, h0, l0);
                split_bf16(s1, h1, l1);
                size_t o = ((size_t)bz * SS + r) * SS + c;
                *(uint32_t*)(g_Phi + o) = pack2(h0, h1);
                *(uint32_t*)(g_Plo + o) = pack2(l0, l1);
            }
}

// ---------------------------------------------------------------------------
// PV: out = P @ V  (A = P[S,S] hi/lo, B = Vt[D,S] hi/lo), fp32 out.
// ---------------------------------------------------------------------------
__global__ void __launch_bounds__(256, 1)
pv_mma(float* __restrict__ out)
{
    extern __shared__ char smem[];
    uint32_t sbase = smem_u32(smem);
    const int bz = blockIdx.z;
    const int mrow = blockIdx.y * 128;
    const int ncol = blockIdx.x * 128;

    const __nv_bfloat16* Ah = g_Phi  + ((size_t)bz * SS + mrow) * SS;
    const __nv_bfloat16* Al = g_Plo  + ((size_t)bz * SS + mrow) * SS;
    const __nv_bfloat16* Bh = g_Vthi + ((size_t)bz * DD + ncol) * SS;
    const __nv_bfloat16* Bl = g_Vtlo + ((size_t)bz * DD + ncol) * SS;

    float acc[16][4];
    gemm_core<SS / 32>(Ah, Al, SS, Bh, Bl, SS, sbase, acc);

    const int lane = threadIdx.x & 31, wid = threadIdx.x >> 5;
    const int warpM = wid >> 1, warpN = wid & 1;

#pragma unroll
    for (int mt = 0; mt < 2; ++mt)
#pragma unroll
        for (int nt = 0; nt < 8; ++nt)
#pragma unroll
            for (int h = 0; h < 2; ++h) {
                int r = mrow + warpM * 32 + mt * 16 + (lane >> 2) + h * 8;
                int c = ncol + warpN * 64 + nt * 8 + (lane & 3) * 2;
                *(float2*)(out + ((size_t)bz * SS + r) * DD + c) =
                    make_float2(acc[mt * 8 + nt][h * 2 + 0], acc[mt * 8 + nt][h * 2 + 1]);
            }
}

// ---------------------------------------------------------------------------
extern "C" void kernel_launch(void* const* d_in, const int* in_sizes, int n_in,
                              void* d_out, int out_size)
{
    const float* x    = (const float*)d_in[0];
    const float* bias = (const float*)d_in[1];
    const float* Wq   = (const float*)d_in[2];
    const float* bq   = (const float*)d_in[3];
    const float* Wk   = (const float*)d_in[4];
    const float* bk   = (const float*)d_in[5];
    const float* Wv   = (const float*)d_in[6];
    const float* bv   = (const float*)d_in[7];
    float* out = (float*)d_out;

    static bool attr_done = false;
    if (!attr_done) {
        cudaFuncSetAttribute(qkv_mma,    cudaFuncAttributeMaxDynamicSharedMemorySize, SMEM_GEMM);
        cudaFuncSetAttribute(scores_mma, cudaFuncAttributeMaxDynamicSharedMemorySize, SMEM_GEMM);
        cudaFuncSetAttribute(pv_mma,     cudaFuncAttributeMaxDynamicSharedMemorySize, SMEM_GEMM);
        attr_done = true;
    }

    __nv_bfloat16 *Whi, *Wlo, *xhi, *xlo;
    cudaGetSymbolAddress((void**)&Whi, g_Whi);
    cudaGetSymbolAddress((void**)&Wlo, g_Wlo);
    cudaGetSymbolAddress((void**)&xhi, g_xhi);
    cudaGetSymbolAddress((void**)&xlo, g_xlo);

    // 0) split x and weights to bf16 hi/lo
    {
        int n4 = M_TOTAL * DD / 4;
        split_kernel<<<(n4 + 255) / 256, 256>>>(x, xhi, xlo, n4);
        int w4 = DD * DD / 4;
        split_kernel<<<(w4 + 255) / 256, 256>>>(Wq, Whi,               Wlo,               w4);
        split_kernel<<<(w4 + 255) / 256, 256>>>(Wk, Whi + DD * DD,     Wlo + DD * DD,     w4);
        split_kernel<<<(w4 + 255) / 256, 256>>>(Wv, Whi + 2 * DD * DD, Wlo + 2 * DD * DD, w4);
    }

    // 1) QKV projections on tensor cores: grid (4, 128, 3)
    qkv_mma<<<dim3(DD / 128, M_TOTAL / 128, 3), 256, SMEM_GEMM>>>(bq, bk, bv);

    // 2) V transpose + split
    vt_kernel<<<dim3(DD / 32, SS / 32, BB), 256>>>();

    // 3) sigmoid scores: grid (32, 32, 4)
    scores_mma<<<dim3(SS / 128, SS / 128, BB), 256, SMEM_GEMM>>>(bias);

    // 4) out = P @ V: grid (4, 32, 4)
    pv_mma<<<dim3(DD / 128, SS / 128, BB), 256, SMEM_GEMM>>>(out);
}

// round 4
// speedup vs baseline: 2.9245x; 1.0668x over previous
#include <cuda_runtime.h>
#include <cuda_bf16.h>
#include <stdint.h>
#include <math.h>

// ---------------------------------------------------------------------------
// Problem constants
// ---------------------------------------------------------------------------
#define BB 4
#define SS 4096
#define DD 512
#define M_TOTAL (BB * SS)   // 16384
#define INV_SQRT_D 0.04419417382415922f

// ---------------------------------------------------------------------------
// Scratch (__device__ globals; allocation-free rule)
// ---------------------------------------------------------------------------
__device__ __align__(256) __nv_bfloat16 g_xhi[(size_t)M_TOTAL * DD];
__device__ __align__(256) __nv_bfloat16 g_xlo[(size_t)M_TOTAL * DD];
__device__ __align__(256) __nv_bfloat16 g_Whi[(size_t)3 * DD * DD];
__device__ __align__(256) __nv_bfloat16 g_Wlo[(size_t)3 * DD * DD];
__device__ __align__(256) __nv_bfloat16 g_Qhi[(size_t)M_TOTAL * DD];
__device__ __align__(256) __nv_bfloat16 g_Qlo[(size_t)M_TOTAL * DD];
__device__ __align__(256) __nv_bfloat16 g_Khi[(size_t)M_TOTAL * DD];
__device__ __align__(256) __nv_bfloat16 g_Klo[(size_t)M_TOTAL * DD];
__device__ __align__(256) float         g_Vf [(size_t)M_TOTAL * DD];
__device__ __align__(256) __nv_bfloat16 g_Vthi[(size_t)BB * DD * SS];  // V^T [b][d][s]
__device__ __align__(256) __nv_bfloat16 g_Vtlo[(size_t)BB * DD * SS];
__device__ __align__(256) __nv_bfloat16 g_Phi[(size_t)BB * SS * SS];
__device__ __align__(256) __nv_bfloat16 g_Plo[(size_t)BB * SS * SS];

// ---------------------------------------------------------------------------
// Helpers
// ---------------------------------------------------------------------------
__device__ __forceinline__ uint32_t smem_u32(const void* p) {
    uint32_t a;
    asm("{ .reg .u64 t; cvta.to.shared.u64 t, %1; cvt.u32.u64 %0, t; }" : "=r"(a) : "l"(p));
    return a;
}

#define CP_ASYNC16(dst, src) \
    asm volatile("cp.async.cg.shared.global [%0], [%1], 16;" :: "r"(dst), "l"(src))
#define CP_COMMIT() asm volatile("cp.async.commit_group;")
#define CP_WAIT1()  asm volatile("cp.async.wait_group 1;" ::: "memory")
#define CP_WAIT0()  asm volatile("cp.async.wait_group 0;" ::: "memory")

__device__ __forceinline__ void ldsm4(uint32_t (&r)[4], uint32_t addr) {
    asm volatile("ldmatrix.sync.aligned.m8n8.x4.shared.b16 {%0,%1,%2,%3}, [%4];"
                 : "=r"(r[0]), "=r"(r[1]), "=r"(r[2]), "=r"(r[3]) : "r"(addr));
}

__device__ __forceinline__ void mma16816(float (&d)[4], const uint32_t (&a)[4],
                                         uint32_t b0, uint32_t b1) {
    asm volatile(
        "mma.sync.aligned.m16n8k16.row.col.f32.bf16.bf16.f32 "
        "{%0,%1,%2,%3}, {%4,%5,%6,%7}, {%8,%9}, {%0,%1,%2,%3};"
        : "+f"(d[0]), "+f"(d[1]), "+f"(d[2]), "+f"(d[3])
        : "r"(a[0]), "r"(a[1]), "r"(a[2]), "r"(a[3]), "r"(b0), "r"(b1));
}

__device__ __forceinline__ void split_bf16(float v, __nv_bfloat16& h, __nv_bfloat16& l) {
    h = __float2bfloat16(v);
    l = __float2bfloat16(v - __bfloat162float(h));
}
__device__ __forceinline__ uint32_t pack2(__nv_bfloat16 a, __nv_bfloat16 b) {
    return ((uint32_t)__bfloat16_as_ushort(b) << 16) | (uint32_t)__bfloat16_as_ushort(a);
}

// ---------------------------------------------------------------------------
// mma.sync GEMM core, CTA tile 256(M) x 128(N), BK=32, 8 warps (4M x 2N of
// 64x64 warp tiles), 3-stage cp.async pipeline, ONE barrier per k-tile.
// NT GEMM: A[M,K] row-major hi/lo, B[N,K] row-major hi/lo.
// SMEM stage 48KB: Ahi(16K) Alo(16K) Bhi(8K) Blo(8K).
// 64B rows, XOR swizzle chunk ^= (row>>1)&3.
// ---------------------------------------------------------------------------
#define STAGE_BYTES 49152
#define SMEM_GEMM (3 * STAGE_BYTES)

__device__ __forceinline__ void load_stage(
    uint32_t sb, const __nv_bfloat16* Ah, const __nv_bfloat16* Al, int lda,
    const __nv_bfloat16* Bh, const __nv_bfloat16* Bl, int ldb, int k0, int tid)
{
#pragma unroll
    for (int it = 0; it < 4; ++it) {           // A: 256 rows * 4 chunks
        int u = it * 256 + tid;
        int row = u >> 2;
        int ch = u & 3;
        uint32_t soff = (uint32_t)row * 64 + ((uint32_t)(ch ^ ((row >> 1) & 3)) << 4);
        CP_ASYNC16(sb +         soff, (const char*)(Ah + (size_t)row * lda + k0) + ch * 16);
        CP_ASYNC16(sb + 16384 + soff, (const char*)(Al + (size_t)row * lda + k0) + ch * 16);
    }
#pragma unroll
    for (int it = 0; it < 2; ++it) {           // B: 128 rows * 4 chunks
        int u = it * 256 + tid;
        int row = u >> 2;
        int ch = u & 3;
        uint32_t soff = (uint32_t)row * 64 + ((uint32_t)(ch ^ ((row >> 1) & 3)) << 4);
        CP_ASYNC16(sb + 32768 + soff, (const char*)(Bh + (size_t)row * ldb + k0) + ch * 16);
        CP_ASYNC16(sb + 40960 + soff, (const char*)(Bl + (size_t)row * ldb + k0) + ch * 16);
    }
}

template<int KTILES>
__device__ __forceinline__ void gemm_core(
    const __nv_bfloat16* __restrict__ Ah, const __nv_bfloat16* __restrict__ Al, int lda,
    const __nv_bfloat16* __restrict__ Bh, const __nv_bfloat16* __restrict__ Bl, int ldb,
    uint32_t sbase, float (&acc)[32][4])
{
    const int tid  = threadIdx.x;
    const int lane = tid & 31;
    const int wid  = tid >> 5;
    const int warpM = wid >> 1;   // 0..3 -> 64 rows each
    const int warpN = wid & 1;    // 0..1 -> 64 cols each

#pragma unroll
    for (int i = 0; i < 32; ++i)
#pragma unroll
        for (int j = 0; j < 4; ++j) acc[i][j] = 0.0f;

    load_stage(sbase, Ah, Al, lda, Bh, Bl, ldb, 0, tid);
    CP_COMMIT();
    if (KTILES > 1) {
        load_stage(sbase + STAGE_BYTES, Ah, Al, lda, Bh, Bl, ldb, 32, tid);
        CP_COMMIT();
    }

    const int arow = warpM * 64 + (lane & 15);
    const uint32_t a_sw = (uint32_t)((arow >> 1) & 3);
    const int ach = lane >> 4;
    const int brow = warpN * 64 + ((lane >> 4) << 3) + (lane & 7);
    const uint32_t b_sw = (uint32_t)((brow >> 1) & 3);
    const int bch = (lane >> 3) & 1;

#pragma unroll 1
    for (int kt = 0; kt < KTILES; ++kt) {
        if (kt + 1 < KTILES) { CP_WAIT1(); } else { CP_WAIT0(); }
        __syncthreads();
        if (kt + 2 < KTILES) {
            load_stage(sbase + (uint32_t)((kt + 2) % 3) * STAGE_BYTES,
                       Ah, Al, lda, Bh, Bl, ldb, (kt + 2) * 32, tid);
            CP_COMMIT();
        }

        uint32_t sb = sbase + (uint32_t)(kt % 3) * STAGE_BYTES;
#pragma unroll
        for (int ks = 0; ks < 2; ++ks) {
            uint32_t ah[4][4], al[4][4], bh[4][4], bl[4][4];
#pragma unroll
            for (int mt = 0; mt < 4; ++mt) {
                uint32_t addr = sb + (uint32_t)(arow + mt * 16) * 64 +
                                (((uint32_t)(ks * 2 + ach)) ^ a_sw) * 16;
                ldsm4(ah[mt], addr);
                ldsm4(al[mt], addr + 16384);
            }
#pragma unroll
            for (int nb = 0; nb < 4; ++nb) {
                uint32_t addr = sb + 32768 + (uint32_t)(brow + nb * 16) * 64 +
                                (((uint32_t)(ks * 2 + bch)) ^ b_sw) * 16;
                ldsm4(bh[nb], addr);
                ldsm4(bl[nb], addr + 8192);
            }
#pragma unroll
            for (int mt = 0; mt < 4; ++mt)
#pragma unroll
                for (int nt = 0; nt < 8; ++nt) {
                    uint32_t h0 = bh[nt >> 1][(nt & 1) * 2];
                    uint32_t h1 = bh[nt >> 1][(nt & 1) * 2 + 1];
                    uint32_t l0 = bl[nt >> 1][(nt & 1) * 2];
                    uint32_t l1 = bl[nt >> 1][(nt & 1) * 2 + 1];
                    mma16816(acc[mt * 8 + nt], ah[mt], h0, h1);   // hi*hi
                    mma16816(acc[mt * 8 + nt], ah[mt], l0, l1);   // hi*lo
                    mma16816(acc[mt * 8 + nt], al[mt], h0, h1);   // lo*hi
                }
        }
    }
}

// ---------------------------------------------------------------------------
// Split kernel: fp32 -> bf16 hi/lo
// ---------------------------------------------------------------------------
__global__ void __launch_bounds__(256)
split_kernel(const float* __restrict__ src, __nv_bfloat16* __restrict__ hi,
             __nv_bfloat16* __restrict__ lo, int n4)
{
    int i = blockIdx.x * 256 + threadIdx.x;
    if (i >= n4) return;
    float4 v = *(const float4*)(src + (size_t)i * 4);
    __nv_bfloat16 h0, l0, h1, l1, h2, l2, h3, l3;
    split_bf16(v.x, h0, l0); split_bf16(v.y, h1, l1);
    split_bf16(v.z, h2, l2); split_bf16(v.w, h3, l3);
    *(uint2*)(hi + (size_t)i * 4) = make_uint2(pack2(h0, h1), pack2(h2, h3));
    *(uint2*)(lo + (size_t)i * 4) = make_uint2(pack2(l0, l1), pack2(l2, l3));
}

// ---------------------------------------------------------------------------
// QKV projection: C = x @ W^T + b, grid.z selects (Q,K,V)
// ---------------------------------------------------------------------------
__global__ void __launch_bounds__(256, 1)
qkv_mma(const float* __restrict__ bq, const float* __restrict__ bk,
        const float* __restrict__ bv)
{
    extern __shared__ char smem[];
    uint32_t sbase = smem_u32(smem);
    const int z = blockIdx.z;
    const int mrow = blockIdx.y * 256;
    const int ncol = blockIdx.x * 128;

    const __nv_bfloat16* Ah = g_xhi + (size_t)mrow * DD;
    const __nv_bfloat16* Al = g_xlo + (size_t)mrow * DD;
    const __nv_bfloat16* Bh = g_Whi + (size_t)z * DD * DD + (size_t)ncol * DD;
    const __nv_bfloat16* Bl = g_Wlo + (size_t)z * DD * DD + (size_t)ncol * DD;

    float acc[32][4];
    gemm_core<DD / 32>(Ah, Al, DD, Bh, Bl, DD, sbase, acc);

    const float* bvec = (z == 0) ? bq : ((z == 1) ? bk : bv);
    const int lane = threadIdx.x & 31, wid = threadIdx.x >> 5;
    const int warpM = wid >> 1, warpN = wid & 1;

#pragma unroll
    for (int mt = 0; mt < 4; ++mt)
#pragma unroll
        for (int nt = 0; nt < 8; ++nt)
#pragma unroll
            for (int h = 0; h < 2; ++h) {
                int r = mrow + warpM * 64 + mt * 16 + (lane >> 2) + h * 8;
                int c = ncol + warpN * 64 + nt * 8 + (lane & 3) * 2;
                float v0 = acc[mt * 8 + nt][h * 2 + 0] + bvec[c];
                float v1 = acc[mt * 8 + nt][h * 2 + 1] + bvec[c + 1];
                size_t o = (size_t)r * DD + c;
                if (z == 2) {
                    *(float2*)(g_Vf + o) = make_float2(v0, v1);
                } else {
                    if (z == 0) { v0 *= INV_SQRT_D; v1 *= INV_SQRT_D; }
                    __nv_bfloat16 h0, l0, h1, l1;
                    split_bf16(v0, h0, l0);
                    split_bf16(v1, h1, l1);
                    __nv_bfloat16* hip = (z == 0) ? g_Qhi : g_Khi;
                    __nv_bfloat16* lop = (z == 0) ? g_Qlo : g_Klo;
                    *(uint32_t*)(hip + o) = pack2(h0, h1);
                    *(uint32_t*)(lop + o) = pack2(l0, l1);
                }
            }
}

// ---------------------------------------------------------------------------
// V transpose + split -> Vt[b][d][s] bf16 hi/lo
// ---------------------------------------------------------------------------
__global__ void __launch_bounds__(256)
vt_kernel()
{
    __shared__ float t[32][33];
    const int bxd = blockIdx.x;
    const int bys = blockIdx.y;
    const int bz  = blockIdx.z;
    const int tx = threadIdx.x & 31;
    const int ty = threadIdx.x >> 5;

    const float* src = g_Vf + (size_t)bz * SS * DD;
#pragma unroll
    for (int i = 0; i < 4; i++) {
        int s = bys * 32 + ty + i * 8;
        t[ty + i * 8][tx] = src[(size_t)s * DD + bxd * 32 + tx];
    }
    __syncthreads();
#pragma unroll
    for (int i = 0; i < 4; i++) {
        int d = bxd * 32 + ty + i * 8;
        float v = t[tx][ty + i * 8];
        __nv_bfloat16 h, l;
        split_bf16(v, h, l);
        size_t o = ((size_t)bz * DD + d) * SS + bys * 32 + tx;
        g_Vthi[o] = h;
        g_Vtlo[o] = l;
    }
}

// ---------------------------------------------------------------------------
// Scores: P = sigmoid(Q K^T + bias)  (Q pre-scaled), split -> Phi/Plo
// ---------------------------------------------------------------------------
__global__ void __launch_bounds__(256, 1)
scores_mma(const float* __restrict__ bias)
{
    extern __shared__ char smem[];
    uint32_t sbase = smem_u32(smem);
    const int bz = blockIdx.z;
    const int mrow = blockIdx.y * 256;
    const int ncol = blockIdx.x * 128;

    const __nv_bfloat16* Ah = g_Qhi + ((size_t)bz * SS + mrow) * DD;
    const __nv_bfloat16* Al = g_Qlo + ((size_t)bz * SS + mrow) * DD;
    const __nv_bfloat16* Bh = g_Khi + ((size_t)bz * SS + ncol) * DD;
    const __nv_bfloat16* Bl = g_Klo + ((size_t)bz * SS + ncol) * DD;

    float acc[32][4];
    gemm_core<DD / 32>(Ah, Al, DD, Bh, Bl, DD, sbase, acc);

    const int lane = threadIdx.x & 31, wid = threadIdx.x >> 5;
    const int warpM = wid >> 1, warpN = wid & 1;

#pragma unroll
    for (int mt = 0; mt < 4; ++mt)
#pragma unroll
        for (int nt = 0; nt < 8; ++nt)
#pragma unroll
            for (int h = 0; h < 2; ++h) {
                int r = mrow + warpM * 64 + mt * 16 + (lane >> 2) + h * 8;
                int c = ncol + warpN * 64 + nt * 8 + (lane & 3) * 2;
                float2 bb = *(const float2*)(bias + (size_t)r * SS + c);
                float v0 = acc[mt * 8 + nt][h * 2 + 0] + bb.x;
                float v1 = acc[mt * 8 + nt][h * 2 + 1] + bb.y;
                float s0 = __fdividef(1.0f, 1.0f + __expf(-v0));
                float s1 = __fdividef(1.0f, 1.0f + __expf(-v1));
                __nv_bfloat16 h0, l0, h1, l1;
                split_bf16(s0, h0, l0);
                split_bf16(s1, h1, l1);
                size_t o = ((size_t)bz * SS + r) * SS + c;
                *(uint32_t*)(g_Phi + o) = pack2(h0, h1);
                *(uint32_t*)(g_Plo + o) = pack2(l0, l1);
            }
}

// ---------------------------------------------------------------------------
// PV: out = P @ V  (A = P[S,S] hi/lo, B = Vt[D,S] hi/lo), fp32 out
// ---------------------------------------------------------------------------
__global__ void __launch_bounds__(256, 1)
pv_mma(float* __restrict__ out)
{
    extern __shared__ char smem[];
    uint32_t sbase = smem_u32(smem);
    const int bz = blockIdx.z;
    const int mrow = blockIdx.y * 256;
    const int ncol = blockIdx.x * 128;

    const __nv_bfloat16* Ah = g_Phi  + ((size_t)bz * SS + mrow) * SS;
    const __nv_bfloat16* Al = g_Plo  + ((size_t)bz * SS + mrow) * SS;
    const __nv_bfloat16* Bh = g_Vthi + ((size_t)bz * DD + ncol) * SS;
    const __nv_bfloat16* Bl = g_Vtlo + ((size_t)bz * DD + ncol) * SS;

    float acc[32][4];
    gemm_core<SS / 32>(Ah, Al, SS, Bh, Bl, SS, sbase, acc);

    const int lane = threadIdx.x & 31, wid = threadIdx.x >> 5;
    const int warpM = wid >> 1, warpN = wid & 1;

#pragma unroll
    for (int mt = 0; mt < 4; ++mt)
#pragma unroll
        for (int nt = 0; nt < 8; ++nt)
#pragma unroll
            for (int h = 0; h < 2; ++h) {
                int r = mrow + warpM * 64 + mt * 16 + (lane >> 2) + h * 8;
                int c = ncol + warpN * 64 + nt * 8 + (lane & 3) * 2;
                *(float2*)(out + ((size_t)bz * SS + r) * DD + c) =
                    make_float2(acc[mt * 8 + nt][h * 2 + 0], acc[mt * 8 + nt][h * 2 + 1]);
            }
}

// ---------------------------------------------------------------------------
extern "C" void kernel_launch(void* const* d_in, const int* in_sizes, int n_in,
                              void* d_out, int out_size)
{
    const float* x    = (const float*)d_in[0];
    const float* bias = (const float*)d_in[1];
    const float* Wq   = (const float*)d_in[2];
    const float* bq   = (const float*)d_in[3];
    const float* Wk   = (const float*)d_in[4];
    const float* bk   = (const float*)d_in[5];
    const float* Wv   = (const float*)d_in[6];
    const float* bv   = (const float*)d_in[7];
    float* out = (float*)d_out;

    cudaFuncSetAttribute(qkv_mma,    cudaFuncAttributeMaxDynamicSharedMemorySize, SMEM_GEMM);
    cudaFuncSetAttribute(scores_mma, cudaFuncAttributeMaxDynamicSharedMemorySize, SMEM_GEMM);
    cudaFuncSetAttribute(pv_mma,     cudaFuncAttributeMaxDynamicSharedMemorySize, SMEM_GEMM);

    __nv_bfloat16 *Whi, *Wlo, *xhi, *xlo;
    cudaGetSymbolAddress((void**)&Whi, g_Whi);
    cudaGetSymbolAddress((void**)&Wlo, g_Wlo);
    cudaGetSymbolAddress((void**)&xhi, g_xhi);
    cudaGetSymbolAddress((void**)&xlo, g_xlo);

    // 0) split x and weights to bf16 hi/lo
    {
        int n4 = M_TOTAL * DD / 4;
        split_kernel<<<(n4 + 255) / 256, 256>>>(x, xhi, xlo, n4);
        int w4 = DD * DD / 4;
        split_kernel<<<(w4 + 255) / 256, 256>>>(Wq, Whi,               Wlo,               w4);
        split_kernel<<<(w4 + 255) / 256, 256>>>(Wk, Whi + DD * DD,     Wlo + DD * DD,     w4);
        split_kernel<<<(w4 + 255) / 256, 256>>>(Wv, Whi + 2 * DD * DD, Wlo + 2 * DD * DD, w4);
    }

    // 1) QKV projections: grid (4, 64, 3)
    qkv_mma<<<dim3(DD / 128, M_TOTAL / 256, 3), 256, SMEM_GEMM>>>(bq, bk, bv);

    // 2) V transpose + split
    vt_kernel<<<dim3(DD / 32, SS / 32, BB), 256>>>();

    // 3) sigmoid scores: grid (32, 16, 4)
    scores_mma<<<dim3(SS / 128, SS / 256, BB), 256, SMEM_GEMM>>>(bias);

    // 4) out = P @ V: grid (4, 16, 4)
    pv_mma<<<dim3(DD / 128, SS / 256, BB), 256, SMEM_GEMM>>>(out);
}

// round 5
// speedup vs baseline: 7.5535x; 2.5829x over previous
#include <cuda_runtime.h>
#include <cuda_fp16.h>
#include <stdint.h>
#include <math.h>

// ---------------------------------------------------------------------------
// Problem constants
// ---------------------------------------------------------------------------
#define BB 4
#define SS 4096
#define DD 512
#define M_TOTAL (BB * SS)   // 16384
#define INV_SQRT_D 0.04419417382415922f

// ---------------------------------------------------------------------------
// Scratch (__device__ globals; allocation-free rule)
// ---------------------------------------------------------------------------
__device__ __align__(256) __half g_xh[(size_t)M_TOTAL * DD];
__device__ __align__(256) __half g_Wh[(size_t)3 * DD * DD];
__device__ __align__(256) __half g_Qh[(size_t)M_TOTAL * DD];     // pre-scaled by 1/sqrt(D)
__device__ __align__(256) __half g_Kh[(size_t)M_TOTAL * DD];
__device__ __align__(256) float  g_Vf[(size_t)M_TOTAL * DD];
__device__ __align__(256) __half g_Vt[(size_t)BB * DD * SS];     // V^T [b][d][s]
__device__ __align__(256) __half g_P [(size_t)BB * SS * SS];     // sigmoid weights

// ---------------------------------------------------------------------------
// Helpers
// ---------------------------------------------------------------------------
__device__ __forceinline__ uint32_t smem_u32(const void* p) {
    uint32_t a;
    asm("{ .reg .u64 t; cvta.to.shared.u64 t, %1; cvt.u32.u64 %0, t; }" : "=r"(a) : "l"(p));
    return a;
}

#define CP_ASYNC16(dst, src) \
    asm volatile("cp.async.cg.shared.global [%0], [%1], 16;" :: "r"(dst), "l"(src))
#define CP_COMMIT() asm volatile("cp.async.commit_group;")
#define CP_WAIT1()  asm volatile("cp.async.wait_group 1;" ::: "memory")
#define CP_WAIT0()  asm volatile("cp.async.wait_group 0;" ::: "memory")

__device__ __forceinline__ void ldsm4(uint32_t (&r)[4], uint32_t addr) {
    asm volatile("ldmatrix.sync.aligned.m8n8.x4.shared.b16 {%0,%1,%2,%3}, [%4];"
                 : "=r"(r[0]), "=r"(r[1]), "=r"(r[2]), "=r"(r[3]) : "r"(addr));
}

__device__ __forceinline__ void mma16816h(float (&d)[4], const uint32_t (&a)[4],
                                          uint32_t b0, uint32_t b1) {
    asm volatile(
        "mma.sync.aligned.m16n8k16.row.col.f32.f16.f16.f32 "
        "{%0,%1,%2,%3}, {%4,%5,%6,%7}, {%8,%9}, {%0,%1,%2,%3};"
        : "+f"(d[0]), "+f"(d[1]), "+f"(d[2]), "+f"(d[3])
        : "r"(a[0]), "r"(a[1]), "r"(a[2]), "r"(a[3]), "r"(b0), "r"(b1));
}

__device__ __forceinline__ uint32_t pack_h2(float a, float b) {
    __half2 h = __floats2half2_rn(a, b);
    return *(uint32_t*)&h;
}

// ---------------------------------------------------------------------------
// fp16 single-pass mma.sync GEMM core.
// CTA tile 256(M) x 128(N), BK=64, 256 threads = 8 warps (4M x 2N, 64x64 warp
// tiles), 3-stage cp.async pipeline, one barrier per k-tile.
// NT GEMM: A[M,K] row-major fp16, B[N,K] row-major fp16.
// SMEM stage 48KB: A 32KB (256 rows x 128B) | B 16KB (128 rows x 128B).
// 128B rows, XOR swizzle: chunk ^= (row & 7).
// ---------------------------------------------------------------------------
#define STAGE_BYTES 49152
#define SMEM_GEMM (3 * STAGE_BYTES)    // 144 KB

__device__ __forceinline__ void load_stage(
    uint32_t sb, const __half* A, int lda, const __half* B, int ldb, int k0, int tid)
{
#pragma unroll
    for (int it = 0; it < 8; ++it) {     // A: 256 rows * 8 chunks = 2048
        int u = it * 256 + tid;
        int row = u >> 3;
        int ch = u & 7;
        uint32_t soff = (uint32_t)row * 128 + ((uint32_t)(ch ^ (row & 7)) << 4);
        CP_ASYNC16(sb + soff, (const char*)(A + (size_t)row * lda + k0) + ch * 16);
    }
#pragma unroll
    for (int it = 0; it < 4; ++it) {     // B: 128 rows * 8 chunks = 1024
        int u = it * 256 + tid;
        int row = u >> 3;
        int ch = u & 7;
        uint32_t soff = (uint32_t)row * 128 + ((uint32_t)(ch ^ (row & 7)) << 4);
        CP_ASYNC16(sb + 32768 + soff, (const char*)(B + (size_t)row * ldb + k0) + ch * 16);
    }
}

template<int KTILES>
__device__ __forceinline__ void gemm_core(
    const __half* __restrict__ A, int lda,
    const __half* __restrict__ B, int ldb,
    uint32_t sbase, float (&acc)[32][4])
{
    const int tid  = threadIdx.x;
    const int lane = tid & 31;
    const int wid  = tid >> 5;
    const int warpM = wid >> 1;   // 0..3
    const int warpN = wid & 1;    // 0..1

#pragma unroll
    for (int i = 0; i < 32; ++i)
#pragma unroll
        for (int j = 0; j < 4; ++j) acc[i][j] = 0.0f;

    load_stage(sbase, A, lda, B, ldb, 0, tid);
    CP_COMMIT();
    if (KTILES > 1) {
        load_stage(sbase + STAGE_BYTES, A, lda, B, ldb, 64, tid);
        CP_COMMIT();
    }

    const int arow_base = warpM * 64 + (lane & 15);
    const int a_kh = lane >> 4;                    // 0/1
    const int brow = warpN * 64 + ((lane >> 4) << 3) + (lane & 7);
    const int b_kh = (lane >> 3) & 1;

#pragma unroll 1
    for (int kt = 0; kt < KTILES; ++kt) {
        if (kt + 1 < KTILES) { CP_WAIT1(); } else { CP_WAIT0(); }
        __syncthreads();
        if (kt + 2 < KTILES) {
            load_stage(sbase + (uint32_t)((kt + 2) % 3) * STAGE_BYTES,
                       A, lda, B, ldb, (kt + 2) * 64, tid);
            CP_COMMIT();
        }

        uint32_t sb = sbase + (uint32_t)(kt % 3) * STAGE_BYTES;
#pragma unroll
        for (int ks = 0; ks < 4; ++ks) {
            uint32_t a[4][4], b[4][4];
#pragma unroll
            for (int mt = 0; mt < 4; ++mt) {
                int r = arow_base + mt * 16;
                uint32_t ch = (uint32_t)(ks * 2 + a_kh) ^ (uint32_t)(r & 7);
                ldsm4(a[mt], sb + (uint32_t)r * 128 + ch * 16);
            }
#pragma unroll
            for (int nb = 0; nb < 4; ++nb) {
                int r = brow + nb * 16;
                uint32_t ch = (uint32_t)(ks * 2 + b_kh) ^ (uint32_t)(r & 7);
                ldsm4(b[nb], sb + 32768 + (uint32_t)r * 128 + ch * 16);
            }
#pragma unroll
            for (int mt = 0; mt < 4; ++mt)
#pragma unroll
                for (int nt = 0; nt < 8; ++nt)
                    mma16816h(acc[mt * 8 + nt], a[mt],
                              b[nt >> 1][(nt & 1) * 2], b[nt >> 1][(nt & 1) * 2 + 1]);
        }
    }
}

// ---------------------------------------------------------------------------
// Convert: fp32 -> fp16
// ---------------------------------------------------------------------------
__global__ void __launch_bounds__(256)
cvt_kernel(const float* __restrict__ src, __half* __restrict__ dst, int n4)
{
    int i = blockIdx.x * 256 + threadIdx.x;
    if (i >= n4) return;
    float4 v = *(const float4*)(src + (size_t)i * 4);
    *(uint2*)(dst + (size_t)i * 4) = make_uint2(pack_h2(v.x, v.y), pack_h2(v.z, v.w));
}

// ---------------------------------------------------------------------------
// QKV projection: C = x @ W^T + b, grid.z selects (Q,K,V)
// ---------------------------------------------------------------------------
__global__ void __launch_bounds__(256, 1)
qkv_mma(const float* __restrict__ bq, const float* __restrict__ bk,
        const float* __restrict__ bv)
{
    extern __shared__ char smem[];
    uint32_t sbase = smem_u32(smem);
    const int z = blockIdx.z;
    const int mrow = blockIdx.y * 256;
    const int ncol = blockIdx.x * 128;

    const __half* A = g_xh + (size_t)mrow * DD;
    const __half* B = g_Wh + (size_t)z * DD * DD + (size_t)ncol * DD;

    float acc[32][4];
    gemm_core<DD / 64>(A, DD, B, DD, sbase, acc);

    const float* bvec = (z == 0) ? bq : ((z == 1) ? bk : bv);
    const int lane = threadIdx.x & 31, wid = threadIdx.x >> 5;
    const int warpM = wid >> 1, warpN = wid & 1;

#pragma unroll
    for (int mt = 0; mt < 4; ++mt)
#pragma unroll
        for (int nt = 0; nt < 8; ++nt)
#pragma unroll
            for (int h = 0; h < 2; ++h) {
                int r = mrow + warpM * 64 + mt * 16 + (lane >> 2) + h * 8;
                int c = ncol + warpN * 64 + nt * 8 + (lane & 3) * 2;
                float v0 = acc[mt * 8 + nt][h * 2 + 0] + bvec[c];
                float v1 = acc[mt * 8 + nt][h * 2 + 1] + bvec[c + 1];
                size_t o = (size_t)r * DD + c;
                if (z == 2) {
                    *(float2*)(g_Vf + o) = make_float2(v0, v1);
                } else if (z == 0) {
                    *(uint32_t*)(g_Qh + o) = pack_h2(v0 * INV_SQRT_D, v1 * INV_SQRT_D);
                } else {
                    *(uint32_t*)(g_Kh + o) = pack_h2(v0, v1);
                }
            }
}

// ---------------------------------------------------------------------------
// V transpose: Vf[b][s][d] fp32 -> Vt[b][d][s] fp16
// ---------------------------------------------------------------------------
__global__ void __launch_bounds__(256)
vt_kernel()
{
    __shared__ float t[32][33];
    const int bxd = blockIdx.x;
    const int bys = blockIdx.y;
    const int bz  = blockIdx.z;
    const int tx = threadIdx.x & 31;
    const int ty = threadIdx.x >> 5;

    const float* src = g_Vf + (size_t)bz * SS * DD;
#pragma unroll
    for (int i = 0; i < 4; i++) {
        int s = bys * 32 + ty + i * 8;
        t[ty + i * 8][tx] = src[(size_t)s * DD + bxd * 32 + tx];
    }
    __syncthreads();
#pragma unroll
    for (int i = 0; i < 4; i++) {
        int d = bxd * 32 + ty + i * 8;
        g_Vt[((size_t)bz * DD + d) * SS + bys * 32 + tx] = __float2half_rn(t[tx][ty + i * 8]);
    }
}

// ---------------------------------------------------------------------------
// Scores: P = sigmoid(Q K^T + bias), Q pre-scaled. fp16 out.
// grid.x = (ncol_tiles=32) * (b=4), b fastest -> bias tile L2-shared across b.
// ---------------------------------------------------------------------------
__global__ void __launch_bounds__(256, 1)
scores_mma(const float* __restrict__ bias)
{
    extern __shared__ char smem[];
    uint32_t sbase = smem_u32(smem);
    const int bz = blockIdx.x & 3;
    const int ncol = (blockIdx.x >> 2) * 128;
    const int mrow = blockIdx.y * 256;

    const __half* A = g_Qh + ((size_t)bz * SS + mrow) * DD;
    const __half* B = g_Kh + ((size_t)bz * SS + ncol) * DD;

    float acc[32][4];
    gemm_core<DD / 64>(A, DD, B, DD, sbase, acc);

    const int lane = threadIdx.x & 31, wid = threadIdx.x >> 5;
    const int warpM = wid >> 1, warpN = wid & 1;

#pragma unroll
    for (int mt = 0; mt < 4; ++mt)
#pragma unroll
        for (int nt = 0; nt < 8; ++nt)
#pragma unroll
            for (int h = 0; h < 2; ++h) {
                int r = mrow + warpM * 64 + mt * 16 + (lane >> 2) + h * 8;
                int c = ncol + warpN * 64 + nt * 8 + (lane & 3) * 2;
                float2 bb = *(const float2*)(bias + (size_t)r * SS + c);
                float v0 = acc[mt * 8 + nt][h * 2 + 0] + bb.x;
                float v1 = acc[mt * 8 + nt][h * 2 + 1] + bb.y;
                float s0 = __fdividef(1.0f, 1.0f + __expf(-v0));
                float s1 = __fdividef(1.0f, 1.0f + __expf(-v1));
                *(uint32_t*)(g_P + ((size_t)bz * SS + r) * SS + c) = pack_h2(s0, s1);
            }
}

// ---------------------------------------------------------------------------
// PV: out = P @ V  (A = P[S,S] fp16, B = Vt[D,S] fp16), fp32 out
// ---------------------------------------------------------------------------
__global__ void __launch_bounds__(256, 1)
pv_mma(float* __restrict__ out)
{
    extern __shared__ char smem[];
    uint32_t sbase = smem_u32(smem);
    const int bz = blockIdx.z;
    const int mrow = blockIdx.y * 256;
    const int ncol = blockIdx.x * 128;

    const __half* A = g_P  + ((size_t)bz * SS + mrow) * SS;
    const __half* B = g_Vt + ((size_t)bz * DD + ncol) * SS;

    float acc[32][4];
    gemm_core<SS / 64>(A, SS, B, SS, sbase, acc);

    const int lane = threadIdx.x & 31, wid = threadIdx.x >> 5;
    const int warpM = wid >> 1, warpN = wid & 1;

#pragma unroll
    for (int mt = 0; mt < 4; ++mt)
#pragma unroll
        for (int nt = 0; nt < 8; ++nt)
#pragma unroll
            for (int h = 0; h < 2; ++h) {
                int r = mrow + warpM * 64 + mt * 16 + (lane >> 2) + h * 8;
                int c = ncol + warpN * 64 + nt * 8 + (lane & 3) * 2;
                *(float2*)(out + ((size_t)bz * SS + r) * DD + c) =
                    make_float2(acc[mt * 8 + nt][h * 2 + 0], acc[mt * 8 + nt][h * 2 + 1]);
            }
}

// ---------------------------------------------------------------------------
extern "C" void kernel_launch(void* const* d_in, const int* in_sizes, int n_in,
                              void* d_out, int out_size)
{
    const float* x    = (const float*)d_in[0];
    const float* bias = (const float*)d_in[1];
    const float* Wq   = (const float*)d_in[2];
    const float* bq   = (const float*)d_in[3];
    const float* Wk   = (const float*)d_in[4];
    const float* bk   = (const float*)d_in[5];
    const float* Wv   = (const float*)d_in[6];
    const float* bv   = (const float*)d_in[7];
    float* out = (float*)d_out;

    cudaFuncSetAttribute(qkv_mma,    cudaFuncAttributeMaxDynamicSharedMemorySize, SMEM_GEMM);
    cudaFuncSetAttribute(scores_mma, cudaFuncAttributeMaxDynamicSharedMemorySize, SMEM_GEMM);
    cudaFuncSetAttribute(pv_mma,     cudaFuncAttributeMaxDynamicSharedMemorySize, SMEM_GEMM);

    __half *xh, *Wh;
    cudaGetSymbolAddress((void**)&xh, g_xh);
    cudaGetSymbolAddress((void**)&Wh, g_Wh);

    // 0) convert inputs to fp16
    {
        int n4 = M_TOTAL * DD / 4;
        cvt_kernel<<<(n4 + 255) / 256, 256>>>(x, xh, n4);
        int w4 = DD * DD / 4;
        cvt_kernel<<<(w4 + 255) / 256, 256>>>(Wq, Wh,               w4);
        cvt_kernel<<<(w4 + 255) / 256, 256>>>(Wk, Wh + DD * DD,     w4);
        cvt_kernel<<<(w4 + 255) / 256, 256>>>(Wv, Wh + 2 * DD * DD, w4);
    }

    // 1) QKV projections: grid (4, 64, 3)
    qkv_mma<<<dim3(DD / 128, M_TOTAL / 256, 3), 256, SMEM_GEMM>>>(bq, bk, bv);

    // 2) V transpose
    vt_kernel<<<dim3(DD / 32, SS / 32, BB), 256>>>();

    // 3) sigmoid scores: grid (128, 16)  [x = ncol*4 + b]
    scores_mma<<<dim3((SS / 128) * BB, SS / 256), 256, SMEM_GEMM>>>(bias);

    // 4) out = P @ V: grid (4, 16, 4)
    pv_mma<<<dim3(DD / 128, SS / 256, BB), 256, SMEM_GEMM>>>(out);
}